// round 2
// baseline (speedup 1.0000x reference)
#include <cuda_runtime.h>
#include <math.h>

#define NE 8
#define DIM 1024
#define FF 4096
#define MAXN 4096
#define MAXP (2*MAXN)

// ---------------- scratch (static device globals; no allocation) ----------------
__device__ int   g_cnt[NE];
__device__ int   g_bucket[NE*MAXN];        // per-expert list of pair ids (tok*2+k)
__device__ float g_pairw[MAXP];            // renormalized gate weight per pair
__device__ float g_h[(size_t)MAXP*FF];     // 128 MB: gelu(x @ fc_w[e]) per pair
__device__ float g_po[(size_t)MAXP*DIM];   // 32 MB: weighted expert output per pair

// ---------------- kernel 0: zero expert counters ----------------
__global__ void k_zero() {
    if (threadIdx.x < NE) g_cnt[threadIdx.x] = 0;
}

// ---------------- kernel 1: gating + routing ----------------
// One block (256 thr = 8 warps) per token. Warp w computes logit for expert w.
__global__ __launch_bounds__(256) void k_gate(const float* __restrict__ x,
                                              const float* __restrict__ gw) {
    int t    = blockIdx.x;
    int wid  = threadIdx.x >> 5;
    int lane = threadIdx.x & 31;
    __shared__ float lg[NE];

    const float* xr = x + (size_t)t * DIM;
    float s = 0.f;
#pragma unroll 8
    for (int j = lane; j < DIM; j += 32) s += xr[j] * gw[j * NE + wid];
#pragma unroll
    for (int o = 16; o; o >>= 1) s += __shfl_xor_sync(0xffffffffu, s, o);
    if (lane == 0) lg[wid] = s;
    __syncthreads();

    if (threadIdx.x == 0) {
        int i1 = 0; float v1 = lg[0];
#pragma unroll
        for (int e = 1; e < NE; e++) if (lg[e] > v1) { v1 = lg[e]; i1 = e; }
        int i2 = -1; float v2 = -1e30f;
#pragma unroll
        for (int e = 0; e < NE; e++) if (e != i1 && lg[e] > v2) { v2 = lg[e]; i2 = e; }
        // top-2 of logits == top-2 of softmax; renormalized weights:
        float r  = expf(v2 - v1);
        float w1 = 1.f / (1.f + r);
        g_pairw[2*t]     = w1;
        g_pairw[2*t + 1] = 1.f - w1;
        int s1 = atomicAdd(&g_cnt[i1], 1); g_bucket[i1*MAXN + s1] = 2*t;
        int s2 = atomicAdd(&g_cnt[i2], 1); g_bucket[i2*MAXN + s2] = 2*t + 1;
    }
}

// ---------------- grouped GEMM tiling: 128x128 tile, BK=16, 8x8 micro-tile ----------------
#define TM 128
#define TN 128
#define BK 16
#define SPAD 4   // smem row pad -> row stride 132 floats

// A: gathered activation rows [cnt, Kdim] (k contiguous, row stride Kdim)
// B: weights [Kdim, TN-space] (n contiguous, row stride Ldb)
//
// Thread map:
//   A load: m = tid & 127, k-quad = (tid >> 7)*4; two float4 at k-quad and k-quad+8
//   B load: n = (tid & 31)*4, k = tid >> 5 (0..7); two float4 at k and k+8
//   Compute: ty = tid >> 4 (0..15) -> rows ty*8..ty*8+7
//            tx = tid & 15        -> cols tx*8..tx*8+7

// kernel 2: h[pid] = gelu_exact( x[tok] @ fc_w[e] )
// grid: (FF/TN, ceil(MAXN/TM), NE)
__global__ __launch_bounds__(256) void k_fc(const float* __restrict__ x,
                                            const float* __restrict__ w) {
    int e   = blockIdx.z;
    int cnt = g_cnt[e];
    int m0  = blockIdx.y * TM;
    if (m0 >= cnt) return;
    int n0  = blockIdx.x * TN;

    __shared__ float As[BK][TM + SPAD];
    __shared__ float Ws[BK][TN + SPAD];
    __shared__ int   pid_s[TM];

    int tid = threadIdx.x;
    if (tid < TM) {
        int m  = m0 + tid;
        int mm = (m < cnt) ? m : (cnt - 1);   // clamp: dup reads OK, writes guarded
        pid_s[tid] = g_bucket[e * MAXN + mm];
    }
    __syncthreads();

    int am = tid & 127;
    int aq = (tid >> 7) * 4;                 // 0 or 4
    int bn = (tid & 31) * 4;
    int bk = tid >> 5;                       // 0..7
    int ty = tid >> 4;
    int tx = tid & 15;

    const float* arow = x + (size_t)(pid_s[am] >> 1) * DIM;  // token row
    const float* wp   = w + (size_t)e * DIM * FF + n0;       // expert weight base

    float acc[8][8];
#pragma unroll
    for (int i = 0; i < 8; i++)
#pragma unroll
        for (int j = 0; j < 8; j++) acc[i][j] = 0.f;

    for (int k0 = 0; k0 < DIM; k0 += BK) {
        float4 a0 = *(const float4*)(arow + k0 + aq);
        float4 a1 = *(const float4*)(arow + k0 + aq + 8);
        float4 b0 = *(const float4*)(wp + (size_t)(k0 + bk)     * FF + bn);
        float4 b1 = *(const float4*)(wp + (size_t)(k0 + bk + 8) * FF + bn);
        As[aq+0][am] = a0.x; As[aq+1][am] = a0.y; As[aq+2][am] = a0.z; As[aq+3][am] = a0.w;
        As[aq+8][am] = a1.x; As[aq+9][am] = a1.y; As[aq+10][am] = a1.z; As[aq+11][am] = a1.w;
        *(float4*)&Ws[bk][bn]     = b0;
        *(float4*)&Ws[bk + 8][bn] = b1;
        __syncthreads();
#pragma unroll
        for (int k = 0; k < BK; k++) {
            float af[8], bf[8];
            *(float4*)&af[0] = *(const float4*)&As[k][ty * 8];
            *(float4*)&af[4] = *(const float4*)&As[k][ty * 8 + 4];
            *(float4*)&bf[0] = *(const float4*)&Ws[k][tx * 8];
            *(float4*)&bf[4] = *(const float4*)&Ws[k][tx * 8 + 4];
#pragma unroll
            for (int i = 0; i < 8; i++)
#pragma unroll
                for (int j = 0; j < 8; j++) acc[i][j] += af[i] * bf[j];
        }
        __syncthreads();
    }

#pragma unroll
    for (int i = 0; i < 8; i++) {
        int mrow = ty * 8 + i;
        if (m0 + mrow < cnt) {
            float* hp = g_h + (size_t)pid_s[mrow] * FF + n0 + tx * 8;
#pragma unroll
            for (int j = 0; j < 8; j++) {
                float v = acc[i][j];
                hp[j] = 0.5f * v * (1.f + erff(v * 0.70710678118654752f)); // exact GELU
            }
        }
    }
}

// kernel 3: po[pid] = pairw[pid] * ( h[pid] @ proj_w[e] )
// grid: (DIM/TN, ceil(MAXN/TM), NE)
__global__ __launch_bounds__(256) void k_proj(const float* __restrict__ w) {
    int e   = blockIdx.z;
    int cnt = g_cnt[e];
    int m0  = blockIdx.y * TM;
    if (m0 >= cnt) return;
    int n0  = blockIdx.x * TN;

    __shared__ float As[BK][TM + SPAD];
    __shared__ float Ws[BK][TN + SPAD];
    __shared__ int   pid_s[TM];

    int tid = threadIdx.x;
    if (tid < TM) {
        int m  = m0 + tid;
        int mm = (m < cnt) ? m : (cnt - 1);
        pid_s[tid] = g_bucket[e * MAXN + mm];
    }
    __syncthreads();

    int am = tid & 127;
    int aq = (tid >> 7) * 4;
    int bn = (tid & 31) * 4;
    int bk = tid >> 5;
    int ty = tid >> 4;
    int tx = tid & 15;

    const float* arow = g_h + (size_t)pid_s[am] * FF;
    const float* wp   = w + (size_t)e * FF * DIM + n0;

    float acc[8][8];
#pragma unroll
    for (int i = 0; i < 8; i++)
#pragma unroll
        for (int j = 0; j < 8; j++) acc[i][j] = 0.f;

    for (int k0 = 0; k0 < FF; k0 += BK) {
        float4 a0 = *(const float4*)(arow + k0 + aq);
        float4 a1 = *(const float4*)(arow + k0 + aq + 8);
        float4 b0 = *(const float4*)(wp + (size_t)(k0 + bk)     * DIM + bn);
        float4 b1 = *(const float4*)(wp + (size_t)(k0 + bk + 8) * DIM + bn);
        As[aq+0][am] = a0.x; As[aq+1][am] = a0.y; As[aq+2][am] = a0.z; As[aq+3][am] = a0.w;
        As[aq+8][am] = a1.x; As[aq+9][am] = a1.y; As[aq+10][am] = a1.z; As[aq+11][am] = a1.w;
        *(float4*)&Ws[bk][bn]     = b0;
        *(float4*)&Ws[bk + 8][bn] = b1;
        __syncthreads();
#pragma unroll
        for (int k = 0; k < BK; k++) {
            float af[8], bf[8];
            *(float4*)&af[0] = *(const float4*)&As[k][ty * 8];
            *(float4*)&af[4] = *(const float4*)&As[k][ty * 8 + 4];
            *(float4*)&bf[0] = *(const float4*)&Ws[k][tx * 8];
            *(float4*)&bf[4] = *(const float4*)&Ws[k][tx * 8 + 4];
#pragma unroll
            for (int i = 0; i < 8; i++)
#pragma unroll
                for (int j = 0; j < 8; j++) acc[i][j] += af[i] * bf[j];
        }
        __syncthreads();
    }

#pragma unroll
    for (int i = 0; i < 8; i++) {
        int mrow = ty * 8 + i;
        if (m0 + mrow < cnt) {
            int pid  = pid_s[mrow];
            float gv = g_pairw[pid];
            float* op = g_po + (size_t)pid * DIM + n0 + tx * 8;
#pragma unroll
            for (int j = 0; j < 8; j++) op[j] = gv * acc[i][j];
        }
    }
}

// ---------------- kernel 4: combine two pair outputs per token ----------------
__global__ void k_comb(float* __restrict__ out, int total4) {
    int i = blockIdx.x * blockDim.x + threadIdx.x;   // over N*DIM/4
    if (i >= total4) return;
    const int RP = DIM / 4;                          // float4s per row
    int t = i / RP, c = i - t * RP;
    const float4* po = (const float4*)g_po;
    float4 u = po[(size_t)(2 * t)     * RP + c];
    float4 v = po[(size_t)(2 * t + 1) * RP + c];
    ((float4*)out)[i] = make_float4(u.x + v.x, u.y + v.y, u.z + v.z, u.w + v.w);
}

// ---------------- launch ----------------
extern "C" void kernel_launch(void* const* d_in, const int* in_sizes, int n_in,
                              void* d_out, int out_size) {
    const float* x   = (const float*)d_in[0];
    const float* gw  = (const float*)d_in[1];
    const float* fcw = (const float*)d_in[2];
    const float* pjw = (const float*)d_in[3];
    float* out = (float*)d_out;

    int N = in_sizes[0] / DIM;   // 4096 tokens

    k_zero<<<1, 32>>>();
    k_gate<<<N, 256>>>(x, gw);

    dim3 gfc(FF / TN, (N + TM - 1) / TM, NE);
    k_fc<<<gfc, 256>>>(x, fcw);

    dim3 gpj(DIM / TN, (N + TM - 1) / TM, NE);
    k_proj<<<gpj, 256>>>(pjw);

    int total4 = N * DIM / 4;
    k_comb<<<(total4 + 255) / 256, 256>>>(out, total4);
}

// round 7
// speedup vs baseline: 2.1685x; 2.1685x over previous
#include <cuda_runtime.h>
#include <math.h>
#include <stdint.h>

#define NE 8
#define DIM 1024
#define FF 4096
#define MAXN 4096
#define MAXP (2*MAXN)

// ---------------- scratch (static device globals; no allocation) ----------------
__device__ int   g_cnt[NE];
__device__ int   g_bucket[NE*MAXN];        // per-expert list of pair ids (tok*2+k)
__device__ float g_pairw[MAXP];            // renormalized gate weight per pair
__device__ float g_h[(size_t)MAXP*FF];     // 128 MB: gelu(x @ fc_w[e]) per pair
__device__ float g_po[(size_t)MAXP*DIM];   // 32 MB: weighted expert output per pair

// ---------------- helpers ----------------
// cvt.rna.tf32.f32: destination is a .b32 register (tf32 = bit pattern), so the
// wrapper must use "=r". Storing the bits back through float-typed smem via
// __uint_as_float is fine — the MMA reinterprets them as tf32.
__device__ __forceinline__ float to_tf32(float x) {
    uint32_t r; asm("cvt.rna.tf32.f32 %0, %1;" : "=r"(r) : "f"(x));
    return __uint_as_float(r);
}

__device__ __forceinline__ void mma_tf32(float c[4], const float a[4], float b0f, float b1f) {
    uint32_t a0 = __float_as_uint(a[0]), a1 = __float_as_uint(a[1]);
    uint32_t a2 = __float_as_uint(a[2]), a3 = __float_as_uint(a[3]);
    uint32_t b0 = __float_as_uint(b0f),  b1 = __float_as_uint(b1f);
    asm volatile(
        "mma.sync.aligned.m16n8k8.row.col.f32.tf32.tf32.f32 "
        "{%0,%1,%2,%3}, {%4,%5,%6,%7}, {%8,%9}, {%0,%1,%2,%3};"
        : "+f"(c[0]), "+f"(c[1]), "+f"(c[2]), "+f"(c[3])
        : "r"(a0), "r"(a1), "r"(a2), "r"(a3), "r"(b0), "r"(b1));
}

// ---------------- kernel 0: zero expert counters ----------------
__global__ void k_zero() {
    if (threadIdx.x < NE) g_cnt[threadIdx.x] = 0;
}

// ---------------- kernel 1: gating + routing ----------------
__global__ __launch_bounds__(256) void k_gate(const float* __restrict__ x,
                                              const float* __restrict__ gw) {
    int t    = blockIdx.x;
    int wid  = threadIdx.x >> 5;
    int lane = threadIdx.x & 31;
    __shared__ float lg[NE];

    const float* xr = x + (size_t)t * DIM;
    float s = 0.f;
#pragma unroll 8
    for (int j = lane; j < DIM; j += 32) s += xr[j] * gw[j * NE + wid];
#pragma unroll
    for (int o = 16; o; o >>= 1) s += __shfl_xor_sync(0xffffffffu, s, o);
    if (lane == 0) lg[wid] = s;
    __syncthreads();

    if (threadIdx.x == 0) {
        int i1 = 0; float v1 = lg[0];
#pragma unroll
        for (int e = 1; e < NE; e++) if (lg[e] > v1) { v1 = lg[e]; i1 = e; }
        int i2 = -1; float v2 = -1e30f;
#pragma unroll
        for (int e = 0; e < NE; e++) if (e != i1 && lg[e] > v2) { v2 = lg[e]; i2 = e; }
        // top-2 of logits == top-2 of softmax; renormalized weights:
        float r  = expf(v2 - v1);
        float w1 = 1.f / (1.f + r);
        g_pairw[2*t]     = w1;
        g_pairw[2*t + 1] = 1.f - w1;
        int s1 = atomicAdd(&g_cnt[i1], 1); g_bucket[i1*MAXN + s1] = 2*t;
        int s2 = atomicAdd(&g_cnt[i2], 1); g_bucket[i2*MAXN + s2] = 2*t + 1;
    }
}

// ---------------- grouped GEMM via tf32 mma.sync ----------------
// Block tile 128x128, BK=16 (two k8 steps). 8 warps as 2x4: warp tile 64x32.
// Per warp: 4 m16 tiles x 4 n8 tiles = 16 mma per k8 step.
// SPAD=8 so smem row stride = 136 floats; 136 mod 32 = 8 makes the scalar
// fragment loads (bank = 8*c + g) conflict-free.
#define TM 128
#define TN 128
#define BK 16
#define SPAD 8

// A-fragment loads for one k8 slice: af[mt][0..3] per mma layout
// a0=(r,c) a1=(r+8,c) a2=(r,c+4) a3=(r+8,c+4); r=lane>>2, c=lane&3.

// kernel 2: h[pid] = gelu_exact( x[tok] @ fc_w[e] )
// grid: (FF/TN, ceil(MAXN/TM), NE)
__global__ __launch_bounds__(256, 2) void k_fc(const float* __restrict__ x,
                                               const float* __restrict__ w) {
    int e   = blockIdx.z;
    int cnt = g_cnt[e];
    int m0  = blockIdx.y * TM;
    if (m0 >= cnt) return;
    int n0  = blockIdx.x * TN;

    __shared__ float As[BK][TM + SPAD];
    __shared__ float Ws[BK][TN + SPAD];
    __shared__ int   pid_s[TM];

    int tid  = threadIdx.x;
    int lane = tid & 31;
    int wid  = tid >> 5;
    int wm   = wid >> 2;          // 0..1 -> rows wm*64
    int wn   = wid & 3;           // 0..3 -> cols wn*32

    if (tid < TM) {
        int m  = m0 + tid;
        int mm = (m < cnt) ? m : (cnt - 1);
        pid_s[tid] = g_bucket[e * MAXN + mm];
    }
    __syncthreads();

    int am = tid & 127;
    int aq = (tid >> 7) * 4;          // 0 or 4
    int bn = (tid & 31) * 4;
    int bk = tid >> 5;                // 0..7

    const float* arow = x + (size_t)(pid_s[am] >> 1) * DIM;
    const float* wp   = w + (size_t)e * DIM * FF + n0;

    float acc[4][4][4];
#pragma unroll
    for (int i = 0; i < 4; i++)
#pragma unroll
        for (int j = 0; j < 4; j++)
#pragma unroll
            for (int q = 0; q < 4; q++) acc[i][j][q] = 0.f;

    int rr = lane >> 2;               // 0..7
    int cc = lane & 3;                // 0..3

    for (int k0 = 0; k0 < DIM; k0 += BK) {
        float4 a0 = *(const float4*)(arow + k0 + aq);
        float4 a1 = *(const float4*)(arow + k0 + aq + 8);
        float4 b0 = *(const float4*)(wp + (size_t)(k0 + bk)     * FF + bn);
        float4 b1 = *(const float4*)(wp + (size_t)(k0 + bk + 8) * FF + bn);
        As[aq+0][am] = to_tf32(a0.x); As[aq+1][am]  = to_tf32(a0.y);
        As[aq+2][am] = to_tf32(a0.z); As[aq+3][am]  = to_tf32(a0.w);
        As[aq+8][am] = to_tf32(a1.x); As[aq+9][am]  = to_tf32(a1.y);
        As[aq+10][am] = to_tf32(a1.z); As[aq+11][am] = to_tf32(a1.w);
        *(float4*)&Ws[bk][bn]     = make_float4(to_tf32(b0.x), to_tf32(b0.y), to_tf32(b0.z), to_tf32(b0.w));
        *(float4*)&Ws[bk + 8][bn] = make_float4(to_tf32(b1.x), to_tf32(b1.y), to_tf32(b1.z), to_tf32(b1.w));
        __syncthreads();
#pragma unroll
        for (int ks = 0; ks < 2; ks++) {
            float af[4][4];
#pragma unroll
            for (int mt = 0; mt < 4; mt++) {
                int mrow = wm * 64 + mt * 16;
                af[mt][0] = As[ks*8 + cc    ][mrow + rr];
                af[mt][1] = As[ks*8 + cc    ][mrow + rr + 8];
                af[mt][2] = As[ks*8 + cc + 4][mrow + rr];
                af[mt][3] = As[ks*8 + cc + 4][mrow + rr + 8];
            }
#pragma unroll
            for (int nt = 0; nt < 4; nt++) {
                int ncol = wn * 32 + nt * 8 + rr;
                float bf0 = Ws[ks*8 + cc    ][ncol];
                float bf1 = Ws[ks*8 + cc + 4][ncol];
#pragma unroll
                for (int mt = 0; mt < 4; mt++)
                    mma_tf32(acc[mt][nt], af[mt], bf0, bf1);
            }
        }
        __syncthreads();
    }

    // epilogue: rows wm*64+mt*16+{rr, rr+8}, cols n0+wn*32+nt*8+2*cc+{0,1}
#pragma unroll
    for (int mt = 0; mt < 4; mt++) {
        int row0 = wm * 64 + mt * 16 + rr;
        int row1 = row0 + 8;
        bool v0 = (m0 + row0 < cnt);
        bool v1 = (m0 + row1 < cnt);
        float* hp0 = v0 ? (g_h + (size_t)pid_s[row0] * FF + n0) : 0;
        float* hp1 = v1 ? (g_h + (size_t)pid_s[row1] * FF + n0) : 0;
#pragma unroll
        for (int nt = 0; nt < 4; nt++) {
            int col = wn * 32 + nt * 8 + 2 * cc;
            if (v0) {
                float u0 = acc[mt][nt][0], u1 = acc[mt][nt][1];
                float2 g2 = make_float2(
                    0.5f * u0 * (1.f + erff(u0 * 0.70710678118654752f)),
                    0.5f * u1 * (1.f + erff(u1 * 0.70710678118654752f)));
                *(float2*)(hp0 + col) = g2;
            }
            if (v1) {
                float u2 = acc[mt][nt][2], u3 = acc[mt][nt][3];
                float2 g2 = make_float2(
                    0.5f * u2 * (1.f + erff(u2 * 0.70710678118654752f)),
                    0.5f * u3 * (1.f + erff(u3 * 0.70710678118654752f)));
                *(float2*)(hp1 + col) = g2;
            }
        }
    }
}

// kernel 3: po[pid] = pairw[pid] * ( h[pid] @ proj_w[e] )
// grid: (DIM/TN, ceil(MAXN/TM), NE)
__global__ __launch_bounds__(256, 2) void k_proj(const float* __restrict__ w) {
    int e   = blockIdx.z;
    int cnt = g_cnt[e];
    int m0  = blockIdx.y * TM;
    if (m0 >= cnt) return;
    int n0  = blockIdx.x * TN;

    __shared__ float As[BK][TM + SPAD];
    __shared__ float Ws[BK][TN + SPAD];
    __shared__ int   pid_s[TM];

    int tid  = threadIdx.x;
    int lane = tid & 31;
    int wid  = tid >> 5;
    int wm   = wid >> 2;
    int wn   = wid & 3;

    if (tid < TM) {
        int m  = m0 + tid;
        int mm = (m < cnt) ? m : (cnt - 1);
        pid_s[tid] = g_bucket[e * MAXN + mm];
    }
    __syncthreads();

    int am = tid & 127;
    int aq = (tid >> 7) * 4;
    int bn = (tid & 31) * 4;
    int bk = tid >> 5;

    const float* arow = g_h + (size_t)pid_s[am] * FF;
    const float* wp   = w + (size_t)e * FF * DIM + n0;

    float acc[4][4][4];
#pragma unroll
    for (int i = 0; i < 4; i++)
#pragma unroll
        for (int j = 0; j < 4; j++)
#pragma unroll
            for (int q = 0; q < 4; q++) acc[i][j][q] = 0.f;

    int rr = lane >> 2;
    int cc = lane & 3;

    for (int k0 = 0; k0 < FF; k0 += BK) {
        float4 a0 = *(const float4*)(arow + k0 + aq);
        float4 a1 = *(const float4*)(arow + k0 + aq + 8);
        float4 b0 = *(const float4*)(wp + (size_t)(k0 + bk)     * DIM + bn);
        float4 b1 = *(const float4*)(wp + (size_t)(k0 + bk + 8) * DIM + bn);
        As[aq+0][am] = to_tf32(a0.x); As[aq+1][am]  = to_tf32(a0.y);
        As[aq+2][am] = to_tf32(a0.z); As[aq+3][am]  = to_tf32(a0.w);
        As[aq+8][am] = to_tf32(a1.x); As[aq+9][am]  = to_tf32(a1.y);
        As[aq+10][am] = to_tf32(a1.z); As[aq+11][am] = to_tf32(a1.w);
        *(float4*)&Ws[bk][bn]     = make_float4(to_tf32(b0.x), to_tf32(b0.y), to_tf32(b0.z), to_tf32(b0.w));
        *(float4*)&Ws[bk + 8][bn] = make_float4(to_tf32(b1.x), to_tf32(b1.y), to_tf32(b1.z), to_tf32(b1.w));
        __syncthreads();
#pragma unroll
        for (int ks = 0; ks < 2; ks++) {
            float af[4][4];
#pragma unroll
            for (int mt = 0; mt < 4; mt++) {
                int mrow = wm * 64 + mt * 16;
                af[mt][0] = As[ks*8 + cc    ][mrow + rr];
                af[mt][1] = As[ks*8 + cc    ][mrow + rr + 8];
                af[mt][2] = As[ks*8 + cc + 4][mrow + rr];
                af[mt][3] = As[ks*8 + cc + 4][mrow + rr + 8];
            }
#pragma unroll
            for (int nt = 0; nt < 4; nt++) {
                int ncol = wn * 32 + nt * 8 + rr;
                float bf0 = Ws[ks*8 + cc    ][ncol];
                float bf1 = Ws[ks*8 + cc + 4][ncol];
#pragma unroll
                for (int mt = 0; mt < 4; mt++)
                    mma_tf32(acc[mt][nt], af[mt], bf0, bf1);
            }
        }
        __syncthreads();
    }

#pragma unroll
    for (int mt = 0; mt < 4; mt++) {
        int row0 = wm * 64 + mt * 16 + rr;
        int row1 = row0 + 8;
        bool v0 = (m0 + row0 < cnt);
        bool v1 = (m0 + row1 < cnt);
        float gv0 = 0.f, gv1 = 0.f;
        float* op0 = 0; float* op1 = 0;
        if (v0) { int p = pid_s[row0]; gv0 = g_pairw[p]; op0 = g_po + (size_t)p * DIM + n0; }
        if (v1) { int p = pid_s[row1]; gv1 = g_pairw[p]; op1 = g_po + (size_t)p * DIM + n0; }
#pragma unroll
        for (int nt = 0; nt < 4; nt++) {
            int col = wn * 32 + nt * 8 + 2 * cc;
            if (v0) *(float2*)(op0 + col) =
                make_float2(gv0 * acc[mt][nt][0], gv0 * acc[mt][nt][1]);
            if (v1) *(float2*)(op1 + col) =
                make_float2(gv1 * acc[mt][nt][2], gv1 * acc[mt][nt][3]);
        }
    }
}

// ---------------- kernel 4: combine two pair outputs per token ----------------
__global__ void k_comb(float* __restrict__ out, int total4) {
    int i = blockIdx.x * blockDim.x + threadIdx.x;   // over N*DIM/4
    if (i >= total4) return;
    const int RP = DIM / 4;
    int t = i / RP, c = i - t * RP;
    const float4* po = (const float4*)g_po;
    float4 u = po[(size_t)(2 * t)     * RP + c];
    float4 v = po[(size_t)(2 * t + 1) * RP + c];
    ((float4*)out)[i] = make_float4(u.x + v.x, u.y + v.y, u.z + v.z, u.w + v.w);
}

// ---------------- launch ----------------
extern "C" void kernel_launch(void* const* d_in, const int* in_sizes, int n_in,
                              void* d_out, int out_size) {
    const float* x   = (const float*)d_in[0];
    const float* gw  = (const float*)d_in[1];
    const float* fcw = (const float*)d_in[2];
    const float* pjw = (const float*)d_in[3];
    float* out = (float*)d_out;

    int N = in_sizes[0] / DIM;   // 4096 tokens

    k_zero<<<1, 32>>>();
    k_gate<<<N, 256>>>(x, gw);

    dim3 gfc(FF / TN, (N + TM - 1) / TM, NE);
    k_fc<<<gfc, 256>>>(x, fcw);

    dim3 gpj(DIM / TN, (N + TM - 1) / TM, NE);
    k_proj<<<gpj, 256>>>(pjw);

    int total4 = N * DIM / 4;
    k_comb<<<(total4 + 255) / 256, 256>>>(out, total4);
}